// round 2
// baseline (speedup 1.0000x reference)
#include <cuda_runtime.h>
#include <math.h>

#define NTRACK 100000
#define DIM    256
#define LMEM   4
#define NHEAD  8
#define HDIM   32

// ---------------- scratch (static __device__ globals: allocation-guard safe) ----
__device__ float g_q  [(size_t)NTRACK * DIM];
__device__ float g_kv [(size_t)NTRACK * LMEM * 2 * DIM];   // [4N, 512] = [k|v]
__device__ float g_ctx[(size_t)NTRACK * DIM];
__device__ float g_ao [(size_t)NTRACK * DIM];
__device__ float g_e  [(size_t)NTRACK * DIM];
__device__ float g_h  [(size_t)NTRACK * DIM];
__device__ float g_e2 [(size_t)NTRACK * DIM];
__device__ float g_s  [(size_t)NTRACK * DIM];

// ---------------- mask dtype detection -----------------------------------------
// jax bool may be serialized as uint8 (mode 0), int32 (mode 1), or float32 (mode 2).
__device__ int g_maskmode;

__global__ void detect_mask_kernel(const unsigned char* __restrict__ m)
{
    __shared__ int s_nonbin, s_oneoff;
    if (threadIdx.x == 0) { s_nonbin = 0; s_oneoff = 0; }
    __syncthreads();
    int nonbin = 0, oneoff = 0;
    // scan first 4096 bytes, 256 threads x 16 bytes
    const int base = threadIdx.x * 16;
#pragma unroll
    for (int j = 0; j < 16; j++) {
        unsigned char b = m[base + j];
        if (b > 1) nonbin = 1;
        else if (b == 1 && ((base + j) & 3) != 0) oneoff = 1;
    }
    if (nonbin) atomicOr(&s_nonbin, 1);
    if (oneoff) atomicOr(&s_oneoff, 1);
    __syncthreads();
    if (threadIdx.x == 0)
        g_maskmode = s_nonbin ? 2 : (s_oneoff ? 0 : 1);
}

__device__ __forceinline__ bool mask_at(const void* __restrict__ m, int i)
{
    const int mode = g_maskmode;
    if (mode == 0) return ((const unsigned char*)m)[i] != 0;
    if (mode == 1) return ((const int*)m)[i] != 0;
    return ((const float*)m)[i] != 0.0f;
}

// ---------------- generic NT GEMM: C[m,n] = sum_k A[m,k]*B[n,k] + bias[n] -------
// A: [M,256] row-major, B: [Nout,256] row-major (PyTorch Linear weight), K=256.
// Tile 128x128, BK=8, 256 threads, 8x8 microtile split 4+4 for conflict-free LDS.
template <int RELU>
__global__ __launch_bounds__(256)
void gemm_nt(const float* __restrict__ A, const float* __restrict__ B,
             const float* __restrict__ bias, float* __restrict__ C,
             int M, int Nout)
{
    __shared__ float As[8][128];
    __shared__ float Bs[8][128];

    const int bm  = blockIdx.y * 128;
    const int bn  = blockIdx.x * 128;
    const int tid = threadIdx.x;
    const int tr  = (tid >> 4) * 4;   // row group base (0..60)
    const int tc  = (tid & 15) * 4;   // col group base (0..60)
    const int lrow = tid >> 1;        // 0..127 load row
    const int lk   = (tid & 1) * 4;   // 0 or 4

    float acc[8][8];
#pragma unroll
    for (int i = 0; i < 8; i++)
#pragma unroll
        for (int j = 0; j < 8; j++) acc[i][j] = 0.f;

    const bool aval = (bm + lrow) < M;
    const float* Aptr = A + (size_t)(bm + lrow) * 256 + lk;
    const float* Bptr = B + (size_t)(bn + lrow) * 256 + lk;

    for (int k0 = 0; k0 < 256; k0 += 8) {
        float4 a4 = aval ? *(const float4*)(Aptr + k0) : make_float4(0.f, 0.f, 0.f, 0.f);
        float4 b4 = *(const float4*)(Bptr + k0);
        __syncthreads();
        As[lk + 0][lrow] = a4.x; As[lk + 1][lrow] = a4.y;
        As[lk + 2][lrow] = a4.z; As[lk + 3][lrow] = a4.w;
        Bs[lk + 0][lrow] = b4.x; Bs[lk + 1][lrow] = b4.y;
        Bs[lk + 2][lrow] = b4.z; Bs[lk + 3][lrow] = b4.w;
        __syncthreads();
#pragma unroll
        for (int kk = 0; kk < 8; kk++) {
            float4 a0 = *(const float4*)&As[kk][tr];
            float4 a1 = *(const float4*)&As[kk][tr + 64];
            float4 b0 = *(const float4*)&Bs[kk][tc];
            float4 b1 = *(const float4*)&Bs[kk][tc + 64];
            float av[8] = {a0.x, a0.y, a0.z, a0.w, a1.x, a1.y, a1.z, a1.w};
            float bv[8] = {b0.x, b0.y, b0.z, b0.w, b1.x, b1.y, b1.z, b1.w};
#pragma unroll
            for (int i = 0; i < 8; i++)
#pragma unroll
                for (int j = 0; j < 8; j++)
                    acc[i][j] += av[i] * bv[j];
        }
    }

    const int c0 = bn + tc;
    const int c1 = bn + tc + 64;
    float4 bias0 = *(const float4*)(bias + c0);
    float4 bias1 = *(const float4*)(bias + c1);
#pragma unroll
    for (int i = 0; i < 8; i++) {
        int row = bm + tr + (i < 4 ? i : 60 + i);
        if (row >= M) continue;
        float4 v0, v1;
        v0.x = acc[i][0] + bias0.x; v0.y = acc[i][1] + bias0.y;
        v0.z = acc[i][2] + bias0.z; v0.w = acc[i][3] + bias0.w;
        v1.x = acc[i][4] + bias1.x; v1.y = acc[i][5] + bias1.y;
        v1.z = acc[i][6] + bias1.z; v1.w = acc[i][7] + bias1.w;
        if (RELU) {
            v0.x = fmaxf(v0.x, 0.f); v0.y = fmaxf(v0.y, 0.f);
            v0.z = fmaxf(v0.z, 0.f); v0.w = fmaxf(v0.w, 0.f);
            v1.x = fmaxf(v1.x, 0.f); v1.y = fmaxf(v1.y, 0.f);
            v1.z = fmaxf(v1.z, 0.f); v1.w = fmaxf(v1.w, 0.f);
        }
        *(float4*)(C + (size_t)row * Nout + c0) = v0;
        *(float4*)(C + (size_t)row * Nout + c1) = v1;
    }
}

// ---------------- tiny attention: warp per track, lane = (head, slot) ---------
__global__ void attn_kernel(const void* __restrict__ mask)
{
    const int warp = threadIdx.x >> 5, lane = threadIdx.x & 31;
    const int track = blockIdx.x * 8 + warp;
    if (track >= NTRACK) return;
    const int h = lane >> 2, l = lane & 3;

    const bool validTrack = !mask_at(mask, track * 4 + 3);

    const float* q = g_q + (size_t)track * 256 + h * 32;
    const float* k = g_kv + ((size_t)track * 4 + l) * 512 + h * 32;
    float dot = 0.f;
#pragma unroll
    for (int i = 0; i < 32; i += 4) {
        float4 qv = *(const float4*)(q + i);
        float4 kv = *(const float4*)(k + i);
        dot += qv.x * kv.x + qv.y * kv.y + qv.z * kv.z + qv.w * kv.w;
    }
    float logit = dot * 0.17677669529663687f;   // 1/sqrt(32)
    if (validTrack && mask_at(mask, track * 4 + l)) logit = -1e9f;

    float m = logit;
    m = fmaxf(m, __shfl_xor_sync(0xFFFFFFFFu, m, 1));
    m = fmaxf(m, __shfl_xor_sync(0xFFFFFFFFu, m, 2));
    float e = expf(logit - m);
    float s = e;
    s += __shfl_xor_sync(0xFFFFFFFFu, s, 1);
    s += __shfl_xor_sync(0xFFFFFFFFu, s, 2);
    float a = e / s;

    const int lbase = lane & ~3;
    float a0 = __shfl_sync(0xFFFFFFFFu, a, lbase + 0);
    float a1 = __shfl_sync(0xFFFFFFFFu, a, lbase + 1);
    float a2 = __shfl_sync(0xFFFFFFFFu, a, lbase + 2);
    float a3 = __shfl_sync(0xFFFFFFFFu, a, lbase + 3);

    // ctx[d] for d = lane*8 .. lane*8+7 (head h = lane/4 matches d/32)
    const size_t vbase = (size_t)track * 4 * 512 + 256 + lane * 8;
#pragma unroll
    for (int c = 0; c < 8; c += 4) {
        float4 v0 = *(const float4*)(g_kv + vbase + 0 * 512 + c);
        float4 v1 = *(const float4*)(g_kv + vbase + 1 * 512 + c);
        float4 v2 = *(const float4*)(g_kv + vbase + 2 * 512 + c);
        float4 v3 = *(const float4*)(g_kv + vbase + 3 * 512 + c);
        float4 o;
        o.x = a0 * v0.x + a1 * v1.x + a2 * v2.x + a3 * v3.x;
        o.y = a0 * v0.y + a1 * v1.y + a2 * v2.y + a3 * v3.y;
        o.z = a0 * v0.z + a1 * v1.z + a2 * v2.z + a3 * v3.z;
        o.w = a0 * v0.w + a1 * v1.w + a2 * v2.w + a3 * v3.w;
        *(float4*)(g_ctx + (size_t)track * 256 + lane * 8 + c) = o;
    }
}

// ---------------- LayerNorm(x + y): warp per row -------------------------------
__device__ __forceinline__ float warp_sum(float v)
{
#pragma unroll
    for (int off = 16; off >= 1; off >>= 1)
        v += __shfl_xor_sync(0xFFFFFFFFu, v, off);
    return v;
}

__global__ void add_ln_kernel(const float* __restrict__ X, const float* __restrict__ Y,
                              const float* __restrict__ gw, const float* __restrict__ gb,
                              float* __restrict__ out)
{
    const int warp = threadIdx.x >> 5, lane = threadIdx.x & 31;
    const int row = blockIdx.x * 8 + warp;
    if (row >= NTRACK) return;
    const size_t base = (size_t)row * 256 + lane * 8;
    float v[8];
    float4 x0 = *(const float4*)(X + base), x1 = *(const float4*)(X + base + 4);
    float4 y0 = *(const float4*)(Y + base), y1 = *(const float4*)(Y + base + 4);
    v[0] = x0.x + y0.x; v[1] = x0.y + y0.y; v[2] = x0.z + y0.z; v[3] = x0.w + y0.w;
    v[4] = x1.x + y1.x; v[5] = x1.y + y1.y; v[6] = x1.z + y1.z; v[7] = x1.w + y1.w;
    float s = 0.f;
#pragma unroll
    for (int j = 0; j < 8; j++) s += v[j];
    float mu = warp_sum(s) * (1.f / 256.f);
    float sq = 0.f;
#pragma unroll
    for (int j = 0; j < 8; j++) { float d = v[j] - mu; sq += d * d; }
    float var = warp_sum(sq) * (1.f / 256.f);
    float r = rsqrtf(var + 1e-5f);
#pragma unroll
    for (int j = 0; j < 8; j++)
        out[base + j] = (v[j] - mu) * r * gw[lane * 8 + j] + gb[lane * 8 + j];
}

// LN2 + valid-select: writes final new_emb
__global__ void add_ln_select_kernel(const float* __restrict__ X, const float* __restrict__ Y,
                                     const float* __restrict__ gw, const float* __restrict__ gb,
                                     const void* __restrict__ mask,
                                     const float* __restrict__ emb,
                                     float* __restrict__ out)
{
    const int warp = threadIdx.x >> 5, lane = threadIdx.x & 31;
    const int row = blockIdx.x * 8 + warp;
    if (row >= NTRACK) return;
    const size_t base = (size_t)row * 256 + lane * 8;
    const bool valid = !mask_at(mask, row * 4 + 3);
    if (!valid) {
        *(float4*)(out + base)     = *(const float4*)(emb + base);
        *(float4*)(out + base + 4) = *(const float4*)(emb + base + 4);
        return;
    }
    float v[8];
    float4 x0 = *(const float4*)(X + base), x1 = *(const float4*)(X + base + 4);
    float4 y0 = *(const float4*)(Y + base), y1 = *(const float4*)(Y + base + 4);
    v[0] = x0.x + y0.x; v[1] = x0.y + y0.y; v[2] = x0.z + y0.z; v[3] = x0.w + y0.w;
    v[4] = x1.x + y1.x; v[5] = x1.y + y1.y; v[6] = x1.z + y1.z; v[7] = x1.w + y1.w;
    float s = 0.f;
#pragma unroll
    for (int j = 0; j < 8; j++) s += v[j];
    float mu = warp_sum(s) * (1.f / 256.f);
    float sq = 0.f;
#pragma unroll
    for (int j = 0; j < 8; j++) { float d = v[j] - mu; sq += d * d; }
    float var = warp_sum(sq) * (1.f / 256.f);
    float r = rsqrtf(var + 1e-5f);
#pragma unroll
    for (int j = 0; j < 8; j++)
        out[base + j] = (v[j] - mu) * r * gw[lane * 8 + j] + gb[lane * 8 + j];
}

// ---------------- bank shift/scatter (float4 granularity) ----------------------
__global__ void bank_kernel(const float* __restrict__ mem_bank,
                            const float* __restrict__ scores,
                            float* __restrict__ out_bank)
{
    const int idx = blockIdx.x * blockDim.x + threadIdx.x;  // N*L*64 float4 slots
    if (idx >= NTRACK * LMEM * 64) return;
    const int n = idx >> 8;          // /256
    const int l = (idx >> 6) & 3;
    const int c = idx & 63;
    const bool saved = scores[n] > 0.f;
    const float4* mb4 = (const float4*)mem_bank;
    float4 val;
    if (saved) {
        if (l < 3) val = mb4[(size_t)n * 256 + (l + 1) * 64 + c];
        else       val = ((const float4*)g_s)[(size_t)n * 64 + c];
    } else {
        val = mb4[idx];
    }
    ((float4*)out_bank)[idx] = val;
}

__global__ void mask_kernel(const void* __restrict__ mask,
                            const float* __restrict__ scores,
                            float* __restrict__ out_mask)
{
    const int idx = blockIdx.x * blockDim.x + threadIdx.x;
    if (idx >= NTRACK * LMEM) return;
    const int n = idx >> 2, l = idx & 3;
    const bool saved = scores[n] > 0.f;
    float v;
    if (saved) v = (l < 3) ? (mask_at(mask, n * 4 + l + 1) ? 1.f : 0.f) : 0.f;
    else       v = mask_at(mask, idx) ? 1.f : 0.f;
    out_mask[idx] = v;
}

// ---------------- launcher ------------------------------------------------------
extern "C" void kernel_launch(void* const* d_in, const int* in_sizes, int n_in,
                              void* d_out, int out_size)
{
    const float*         emb    = (const float*)d_in[0];
    const float*         scores = (const float*)d_in[1];
    const float*         bank   = (const float*)d_in[2];
    const void*          mask   = (const void*)d_in[3];
    const float*         save_w = (const float*)d_in[4];
    const float*         save_b = (const float*)d_in[5];
    const float*         in_w   = (const float*)d_in[6];
    const float*         in_b   = (const float*)d_in[7];
    const float*         out_w  = (const float*)d_in[8];
    const float*         out_b  = (const float*)d_in[9];
    const float*         fc1_w  = (const float*)d_in[10];
    const float*         fc1_b  = (const float*)d_in[11];
    const float*         fc2_w  = (const float*)d_in[12];
    const float*         fc2_b  = (const float*)d_in[13];
    const float*         ln1_g  = (const float*)d_in[14];
    const float*         ln1_b  = (const float*)d_in[15];
    const float*         ln2_g  = (const float*)d_in[16];
    const float*         ln2_b  = (const float*)d_in[17];

    float* out_emb  = (float*)d_out;
    float* out_bank = out_emb + (size_t)NTRACK * DIM;
    float* out_mask = out_bank + (size_t)NTRACK * LMEM * DIM;

    float *pq, *pkv, *pctx, *pao, *pe, *ph, *pe2, *ps;
    cudaGetSymbolAddress((void**)&pq,  g_q);
    cudaGetSymbolAddress((void**)&pkv, g_kv);
    cudaGetSymbolAddress((void**)&pctx, g_ctx);
    cudaGetSymbolAddress((void**)&pao, g_ao);
    cudaGetSymbolAddress((void**)&pe,  g_e);
    cudaGetSymbolAddress((void**)&ph,  g_h);
    cudaGetSymbolAddress((void**)&pe2, g_e2);
    cudaGetSymbolAddress((void**)&ps,  g_s);

    dim3 gN(2, (NTRACK + 127) / 128);            // Nout=256 GEMMs
    dim3 gKV(4, (NTRACK * LMEM + 127) / 128);    // Nout=512, M=4N

    // detect mask dtype (uint8 / int32 / float32)
    detect_mask_kernel<<<1, 256>>>((const unsigned char*)mask);
    // q = emb @ Wq^T + bq
    gemm_nt<0><<<gN, 256>>>(emb, in_w, in_b, pq, NTRACK, 256);
    // [k|v] = mem_bank(4N,256) @ Wkv^T + bkv
    gemm_nt<0><<<gKV, 256>>>(bank, in_w + 256 * 256, in_b + 256, pkv, NTRACK * LMEM, 512);
    // attention -> ctx
    attn_kernel<<<(NTRACK + 7) / 8, 256>>>(mask);
    // attn_out = ctx @ Wo^T + bo
    gemm_nt<0><<<gN, 256>>>(pctx, out_w, out_b, pao, NTRACK, 256);
    // e = LN1(emb + attn_out)
    add_ln_kernel<<<(NTRACK + 7) / 8, 256>>>(emb, pao, ln1_g, ln1_b, pe);
    // h = relu(e @ W1^T + b1)
    gemm_nt<1><<<gN, 256>>>(pe, fc1_w, fc1_b, ph, NTRACK, 256);
    // e2 = h @ W2^T + b2
    gemm_nt<0><<<gN, 256>>>(ph, fc2_w, fc2_b, pe2, NTRACK, 256);
    // new_emb = valid ? LN2(e + e2) : emb   (written directly to output)
    add_ln_select_kernel<<<(NTRACK + 7) / 8, 256>>>(pe, pe2, ln2_g, ln2_b, mask, emb, out_emb);
    // save_embed = new_emb @ Wsave^T + bsave
    gemm_nt<0><<<gN, 256>>>(out_emb, save_w, save_b, ps, NTRACK, 256);
    // bank shift/scatter + mask
    bank_kernel<<<(NTRACK * LMEM * 64 + 255) / 256, 256>>>(bank, scores, out_bank);
    mask_kernel<<<(NTRACK * LMEM + 255) / 256, 256>>>(mask, scores, out_mask);
}

// round 3
// speedup vs baseline: 1.8119x; 1.8119x over previous
#include <cuda_runtime.h>
#include <math.h>

#define NTRACK 100000
#define DIM    256
#define LMEM   4
#define NHEAD  8
#define HDIM   32

// ---------------- scratch (static __device__ globals: allocation-guard safe) ----
__device__ float g_q  [(size_t)NTRACK * DIM];
__device__ float g_kv [(size_t)NTRACK * LMEM * 2 * DIM];   // compact [4*cnt, 512] = [k|v]
__device__ float g_ctx[(size_t)NTRACK * DIM];
__device__ float g_ao [(size_t)NTRACK * DIM];
__device__ float g_e  [(size_t)NTRACK * DIM];
__device__ float g_h  [(size_t)NTRACK * DIM];
__device__ float g_e2 [(size_t)NTRACK * DIM];
__device__ float g_s  [(size_t)NTRACK * DIM];              // scattered by ORIGINAL row
__device__ int   g_idxv[NTRACK];
__device__ int   g_idxs[NTRACK];
__device__ int   g_cnt[2];          // [0]=valid count, [1]=saved count
__device__ int   g_maskmode;

// ---------------- mask dtype detection -----------------------------------------
__global__ void detect_mask_kernel(const unsigned char* __restrict__ m)
{
    __shared__ int s_nonbin, s_oneoff;
    if (threadIdx.x == 0) { s_nonbin = 0; s_oneoff = 0; }
    __syncthreads();
    int nonbin = 0, oneoff = 0;
    const int base = threadIdx.x * 16;
#pragma unroll
    for (int j = 0; j < 16; j++) {
        unsigned char b = m[base + j];
        if (b > 1) nonbin = 1;
        else if (b == 1 && ((base + j) & 3) != 0) oneoff = 1;
    }
    if (nonbin) atomicOr(&s_nonbin, 1);
    if (oneoff) atomicOr(&s_oneoff, 1);
    __syncthreads();
    if (threadIdx.x == 0) {
        g_maskmode = s_nonbin ? 2 : (s_oneoff ? 0 : 1);
        g_cnt[0] = 0;
        g_cnt[1] = 0;
    }
}

__device__ __forceinline__ bool mask_at(const void* __restrict__ m, int i)
{
    const int mode = g_maskmode;
    if (mode == 0) return ((const unsigned char*)m)[i] != 0;
    if (mode == 1) return ((const int*)m)[i] != 0;
    return ((const float*)m)[i] != 0.0f;
}

// ---------------- compaction: valid tracks & saved tracks ----------------------
__global__ void compact_kernel(const void* __restrict__ mask,
                               const float* __restrict__ scores)
{
    const int n = blockIdx.x * blockDim.x + threadIdx.x;
    bool v = false, sv = false;
    if (n < NTRACK) {
        v  = !mask_at(mask, n * 4 + 3);
        sv = scores[n] > 0.f;
    }
    const unsigned bv = __ballot_sync(0xFFFFFFFFu, v);
    const unsigned bs = __ballot_sync(0xFFFFFFFFu, sv);
    const int lane = threadIdx.x & 31;
    int basev = 0, bases = 0;
    if (lane == 0) {
        if (bv) basev = atomicAdd(&g_cnt[0], __popc(bv));
        if (bs) bases = atomicAdd(&g_cnt[1], __popc(bs));
    }
    basev = __shfl_sync(0xFFFFFFFFu, basev, 0);
    bases = __shfl_sync(0xFFFFFFFFu, bases, 0);
    const unsigned lt = (1u << lane) - 1u;
    if (v)  g_idxv[basev + __popc(bv & lt)] = n;
    if (sv) g_idxs[bases + __popc(bs & lt)] = n;
}

// ---------------- generic NT GEMM with row indirection --------------------------
// C[i,n] = sum_k A[map(i),k]*B[n,k] + bias[n];  store to row cmap(i).
// AMODE 0: identity; 1: idx[i]; 2: idx[i/4]*4 + i%4 (KV gather)
// CMODE 0: identity; 1: idx[i]
// M = (*Mcnt) * mmul. Blocks past M early-exit (fixed grid, graph-capturable).
template <int RELU, int AMODE, int CMODE>
__global__ __launch_bounds__(256)
void gemm_nt(const float* __restrict__ A, const float* __restrict__ B,
             const float* __restrict__ bias, float* __restrict__ C,
             const int* __restrict__ Mcnt, int mmul, int Nout,
             const int* __restrict__ idx)
{
    const int M = (*Mcnt) * mmul;
    const int bm = blockIdx.y * 128;
    if (bm >= M) return;
    const int bn  = blockIdx.x * 128;
    const int tid = threadIdx.x;
    const int tr  = (tid >> 4) * 4;
    const int tc  = (tid & 15) * 4;
    const int lrow = tid >> 1;
    const int lk   = (tid & 1) * 4;

    __shared__ float As[8][128];
    __shared__ float Bs[8][128];

    float acc[8][8];
#pragma unroll
    for (int i = 0; i < 8; i++)
#pragma unroll
        for (int j = 0; j < 8; j++) acc[i][j] = 0.f;

    const int lrow_g = bm + lrow;
    const bool aval = lrow_g < M;
    int arow = 0;
    if (aval) {
        if (AMODE == 0)      arow = lrow_g;
        else if (AMODE == 1) arow = idx[lrow_g];
        else                 arow = idx[lrow_g >> 2] * 4 + (lrow_g & 3);
    }
    const float* Aptr = A + (size_t)arow * 256 + lk;
    const float* Bptr = B + (size_t)(bn + lrow) * 256 + lk;

    for (int k0 = 0; k0 < 256; k0 += 8) {
        float4 a4 = aval ? *(const float4*)(Aptr + k0) : make_float4(0.f, 0.f, 0.f, 0.f);
        float4 b4 = *(const float4*)(Bptr + k0);
        __syncthreads();
        As[lk + 0][lrow] = a4.x; As[lk + 1][lrow] = a4.y;
        As[lk + 2][lrow] = a4.z; As[lk + 3][lrow] = a4.w;
        Bs[lk + 0][lrow] = b4.x; Bs[lk + 1][lrow] = b4.y;
        Bs[lk + 2][lrow] = b4.z; Bs[lk + 3][lrow] = b4.w;
        __syncthreads();
#pragma unroll
        for (int kk = 0; kk < 8; kk++) {
            float4 a0 = *(const float4*)&As[kk][tr];
            float4 a1 = *(const float4*)&As[kk][tr + 64];
            float4 b0 = *(const float4*)&Bs[kk][tc];
            float4 b1 = *(const float4*)&Bs[kk][tc + 64];
            float av[8] = {a0.x, a0.y, a0.z, a0.w, a1.x, a1.y, a1.z, a1.w};
            float bv[8] = {b0.x, b0.y, b0.z, b0.w, b1.x, b1.y, b1.z, b1.w};
#pragma unroll
            for (int i = 0; i < 8; i++)
#pragma unroll
                for (int j = 0; j < 8; j++)
                    acc[i][j] += av[i] * bv[j];
        }
    }

    const int c0 = bn + tc;
    const int c1 = bn + tc + 64;
    float4 bias0 = *(const float4*)(bias + c0);
    float4 bias1 = *(const float4*)(bias + c1);
#pragma unroll
    for (int i = 0; i < 8; i++) {
        int rlog = bm + tr + (i < 4 ? i : 60 + i);
        if (rlog >= M) continue;
        int row = (CMODE == 1) ? idx[rlog] : rlog;
        float4 v0, v1;
        v0.x = acc[i][0] + bias0.x; v0.y = acc[i][1] + bias0.y;
        v0.z = acc[i][2] + bias0.z; v0.w = acc[i][3] + bias0.w;
        v1.x = acc[i][4] + bias1.x; v1.y = acc[i][5] + bias1.y;
        v1.z = acc[i][6] + bias1.z; v1.w = acc[i][7] + bias1.w;
        if (RELU) {
            v0.x = fmaxf(v0.x, 0.f); v0.y = fmaxf(v0.y, 0.f);
            v0.z = fmaxf(v0.z, 0.f); v0.w = fmaxf(v0.w, 0.f);
            v1.x = fmaxf(v1.x, 0.f); v1.y = fmaxf(v1.y, 0.f);
            v1.z = fmaxf(v1.z, 0.f); v1.w = fmaxf(v1.w, 0.f);
        }
        *(float4*)(C + (size_t)row * Nout + c0) = v0;
        *(float4*)(C + (size_t)row * Nout + c1) = v1;
    }
}

// ---------------- tiny attention over compact valid tracks ---------------------
__global__ void attn_kernel(const void* __restrict__ mask)
{
    const int warp = threadIdx.x >> 5, lane = threadIdx.x & 31;
    const int i = blockIdx.x * 8 + warp;
    if (i >= g_cnt[0]) return;
    const int track = g_idxv[i];
    const int h = lane >> 2, l = lane & 3;

    const float* q = g_q + (size_t)i * 256 + h * 32;
    const float* k = g_kv + ((size_t)i * 4 + l) * 512 + h * 32;
    float dot = 0.f;
#pragma unroll
    for (int j = 0; j < 32; j += 4) {
        float4 qv = *(const float4*)(q + j);
        float4 kv = *(const float4*)(k + j);
        dot += qv.x * kv.x + qv.y * kv.y + qv.z * kv.z + qv.w * kv.w;
    }
    float logit = dot * 0.17677669529663687f;   // 1/sqrt(32)
    if (mask_at(mask, track * 4 + l)) logit = -1e9f;

    float m = logit;
    m = fmaxf(m, __shfl_xor_sync(0xFFFFFFFFu, m, 1));
    m = fmaxf(m, __shfl_xor_sync(0xFFFFFFFFu, m, 2));
    float e = expf(logit - m);
    float s = e;
    s += __shfl_xor_sync(0xFFFFFFFFu, s, 1);
    s += __shfl_xor_sync(0xFFFFFFFFu, s, 2);
    float a = e / s;

    const int lbase = lane & ~3;
    float a0 = __shfl_sync(0xFFFFFFFFu, a, lbase + 0);
    float a1 = __shfl_sync(0xFFFFFFFFu, a, lbase + 1);
    float a2 = __shfl_sync(0xFFFFFFFFu, a, lbase + 2);
    float a3 = __shfl_sync(0xFFFFFFFFu, a, lbase + 3);

    const size_t vbase = (size_t)i * 4 * 512 + 256 + lane * 8;
#pragma unroll
    for (int c = 0; c < 8; c += 4) {
        float4 v0 = *(const float4*)(g_kv + vbase + 0 * 512 + c);
        float4 v1 = *(const float4*)(g_kv + vbase + 1 * 512 + c);
        float4 v2 = *(const float4*)(g_kv + vbase + 2 * 512 + c);
        float4 v3 = *(const float4*)(g_kv + vbase + 3 * 512 + c);
        float4 o;
        o.x = a0 * v0.x + a1 * v1.x + a2 * v2.x + a3 * v3.x;
        o.y = a0 * v0.y + a1 * v1.y + a2 * v2.y + a3 * v3.y;
        o.z = a0 * v0.z + a1 * v1.z + a2 * v2.z + a3 * v3.z;
        o.w = a0 * v0.w + a1 * v1.w + a2 * v2.w + a3 * v3.w;
        *(float4*)(g_ctx + (size_t)i * 256 + lane * 8 + c) = o;
    }
}

// ---------------- LayerNorms (compact domain) -----------------------------------
__device__ __forceinline__ float warp_sum(float v)
{
#pragma unroll
    for (int off = 16; off >= 1; off >>= 1)
        v += __shfl_xor_sync(0xFFFFFFFFu, v, off);
    return v;
}

// LN1: out[i] = LN(emb[idx[i]] + g_ao[i])
__global__ void add_ln_kernel(const float* __restrict__ X, const float* __restrict__ Y,
                              const float* __restrict__ gw, const float* __restrict__ gb,
                              float* __restrict__ out)
{
    const int warp = threadIdx.x >> 5, lane = threadIdx.x & 31;
    const int i = blockIdx.x * 8 + warp;
    if (i >= g_cnt[0]) return;
    const size_t xb = (size_t)g_idxv[i] * 256 + lane * 8;
    const size_t yb = (size_t)i * 256 + lane * 8;
    float v[8];
    float4 x0 = *(const float4*)(X + xb), x1 = *(const float4*)(X + xb + 4);
    float4 y0 = *(const float4*)(Y + yb), y1 = *(const float4*)(Y + yb + 4);
    v[0] = x0.x + y0.x; v[1] = x0.y + y0.y; v[2] = x0.z + y0.z; v[3] = x0.w + y0.w;
    v[4] = x1.x + y1.x; v[5] = x1.y + y1.y; v[6] = x1.z + y1.z; v[7] = x1.w + y1.w;
    float s = 0.f;
#pragma unroll
    for (int j = 0; j < 8; j++) s += v[j];
    float mu = warp_sum(s) * (1.f / 256.f);
    float sq = 0.f;
#pragma unroll
    for (int j = 0; j < 8; j++) { float d = v[j] - mu; sq += d * d; }
    float r = rsqrtf(warp_sum(sq) * (1.f / 256.f) + 1e-5f);
#pragma unroll
    for (int j = 0; j < 8; j++)
        out[yb + j] = (v[j] - mu) * r * gw[lane * 8 + j] + gb[lane * 8 + j];
}

// LN2 + scatter: out_emb[idx[i]] = LN(g_e[i] + g_e2[i])
__global__ void ln2_scatter_kernel(const float* __restrict__ X, const float* __restrict__ Y,
                                   const float* __restrict__ gw, const float* __restrict__ gb,
                                   float* __restrict__ out)
{
    const int warp = threadIdx.x >> 5, lane = threadIdx.x & 31;
    const int i = blockIdx.x * 8 + warp;
    if (i >= g_cnt[0]) return;
    const size_t cb = (size_t)i * 256 + lane * 8;
    const size_t ob = (size_t)g_idxv[i] * 256 + lane * 8;
    float v[8];
    float4 x0 = *(const float4*)(X + cb), x1 = *(const float4*)(X + cb + 4);
    float4 y0 = *(const float4*)(Y + cb), y1 = *(const float4*)(Y + cb + 4);
    v[0] = x0.x + y0.x; v[1] = x0.y + y0.y; v[2] = x0.z + y0.z; v[3] = x0.w + y0.w;
    v[4] = x1.x + y1.x; v[5] = x1.y + y1.y; v[6] = x1.z + y1.z; v[7] = x1.w + y1.w;
    float s = 0.f;
#pragma unroll
    for (int j = 0; j < 8; j++) s += v[j];
    float mu = warp_sum(s) * (1.f / 256.f);
    float sq = 0.f;
#pragma unroll
    for (int j = 0; j < 8; j++) { float d = v[j] - mu; sq += d * d; }
    float r = rsqrtf(warp_sum(sq) * (1.f / 256.f) + 1e-5f);
#pragma unroll
    for (int j = 0; j < 8; j++)
        out[ob + j] = (v[j] - mu) * r * gw[lane * 8 + j] + gb[lane * 8 + j];
}

// invalid rows: out_emb[n] = emb[n]
__global__ void copy_invalid_kernel(const float* __restrict__ emb,
                                    const void* __restrict__ mask,
                                    float* __restrict__ out)
{
    const int idx = blockIdx.x * blockDim.x + threadIdx.x;  // N*64 float4 slots
    if (idx >= NTRACK * 64) return;
    const int n = idx >> 6;
    if (!mask_at(mask, n * 4 + 3)) return;   // valid -> written by ln2_scatter
    ((float4*)out)[idx] = ((const float4*)emb)[idx];
}

// ---------------- bank shift/scatter --------------------------------------------
__global__ void bank_kernel(const float* __restrict__ mem_bank,
                            const float* __restrict__ scores,
                            float* __restrict__ out_bank)
{
    const int idx = blockIdx.x * blockDim.x + threadIdx.x;  // N*L*64 float4 slots
    if (idx >= NTRACK * LMEM * 64) return;
    const int n = idx >> 8;
    const int l = (idx >> 6) & 3;
    const int c = idx & 63;
    const bool saved = scores[n] > 0.f;
    const float4* mb4 = (const float4*)mem_bank;
    float4 val;
    if (saved) {
        if (l < 3) val = mb4[(size_t)n * 256 + (l + 1) * 64 + c];
        else       val = ((const float4*)g_s)[(size_t)n * 64 + c];
    } else {
        val = mb4[idx];
    }
    ((float4*)out_bank)[idx] = val;
}

__global__ void mask_kernel(const void* __restrict__ mask,
                            const float* __restrict__ scores,
                            float* __restrict__ out_mask)
{
    const int idx = blockIdx.x * blockDim.x + threadIdx.x;
    if (idx >= NTRACK * LMEM) return;
    const int n = idx >> 2, l = idx & 3;
    const bool saved = scores[n] > 0.f;
    float v;
    if (saved) v = (l < 3) ? (mask_at(mask, n * 4 + l + 1) ? 1.f : 0.f) : 0.f;
    else       v = mask_at(mask, idx) ? 1.f : 0.f;
    out_mask[idx] = v;
}

// ---------------- launcher ------------------------------------------------------
extern "C" void kernel_launch(void* const* d_in, const int* in_sizes, int n_in,
                              void* d_out, int out_size)
{
    const float* emb    = (const float*)d_in[0];
    const float* scores = (const float*)d_in[1];
    const float* bank   = (const float*)d_in[2];
    const void*  mask   = (const void*)d_in[3];
    const float* save_w = (const float*)d_in[4];
    const float* save_b = (const float*)d_in[5];
    const float* in_w   = (const float*)d_in[6];
    const float* in_b   = (const float*)d_in[7];
    const float* out_w  = (const float*)d_in[8];
    const float* out_b  = (const float*)d_in[9];
    const float* fc1_w  = (const float*)d_in[10];
    const float* fc1_b  = (const float*)d_in[11];
    const float* fc2_w  = (const float*)d_in[12];
    const float* fc2_b  = (const float*)d_in[13];
    const float* ln1_g  = (const float*)d_in[14];
    const float* ln1_b  = (const float*)d_in[15];
    const float* ln2_g  = (const float*)d_in[16];
    const float* ln2_b  = (const float*)d_in[17];

    float* out_emb  = (float*)d_out;
    float* out_bank = out_emb + (size_t)NTRACK * DIM;
    float* out_mask = out_bank + (size_t)NTRACK * LMEM * DIM;

    float *pq, *pkv, *pctx, *pao, *pe, *ph, *pe2, *ps;
    int *pidxv, *pidxs, *pcnt;
    cudaGetSymbolAddress((void**)&pq,   g_q);
    cudaGetSymbolAddress((void**)&pkv,  g_kv);
    cudaGetSymbolAddress((void**)&pctx, g_ctx);
    cudaGetSymbolAddress((void**)&pao,  g_ao);
    cudaGetSymbolAddress((void**)&pe,   g_e);
    cudaGetSymbolAddress((void**)&ph,   g_h);
    cudaGetSymbolAddress((void**)&pe2,  g_e2);
    cudaGetSymbolAddress((void**)&ps,   g_s);
    cudaGetSymbolAddress((void**)&pidxv, g_idxv);
    cudaGetSymbolAddress((void**)&pidxs, g_idxs);
    cudaGetSymbolAddress((void**)&pcnt,  g_cnt);

    const dim3 gN(2, (NTRACK + 127) / 128);          // Nout=256, M<=N
    const dim3 gKV(4, (NTRACK * LMEM + 127) / 128);  // Nout=512, M<=4N
    const int rowBlocks = (NTRACK + 7) / 8;

    // mask dtype + counter reset, then compaction
    detect_mask_kernel<<<1, 256>>>((const unsigned char*)mask);
    compact_kernel<<<(NTRACK + 255) / 256, 256>>>(mask, scores);

    // q = emb[valid] @ Wq^T + bq            (gather-A)
    gemm_nt<0, 1, 0><<<gN, 256>>>(emb, in_w, in_b, pq, pcnt, 1, 256, pidxv);
    // [k|v] = bank[valid tracks] @ Wkv^T    (gather-A mode 2, M=4*cnt)
    gemm_nt<0, 2, 0><<<gKV, 256>>>(bank, in_w + 256 * 256, in_b + 256, pkv, pcnt, 4, 512, pidxv);
    // attention -> ctx (compact)
    attn_kernel<<<rowBlocks, 256>>>(mask);
    // attn_out = ctx @ Wo^T + bo (compact)
    gemm_nt<0, 0, 0><<<gN, 256>>>(pctx, out_w, out_b, pao, pcnt, 1, 256, pidxv);
    // e = LN1(emb[idx] + attn_out) (compact)
    add_ln_kernel<<<rowBlocks, 256>>>(emb, pao, ln1_g, ln1_b, pe);
    // h = relu(e @ W1^T + b1) (compact)
    gemm_nt<1, 0, 0><<<gN, 256>>>(pe, fc1_w, fc1_b, ph, pcnt, 1, 256, pidxv);
    // e2 = h @ W2^T + b2 (compact)
    gemm_nt<0, 0, 0><<<gN, 256>>>(ph, fc2_w, fc2_b, pe2, pcnt, 1, 256, pidxv);
    // new_emb: valid rows LN2-scattered, invalid rows copied
    ln2_scatter_kernel<<<rowBlocks, 256>>>(pe, pe2, ln2_g, ln2_b, out_emb);
    copy_invalid_kernel<<<(NTRACK * 64 + 255) / 256, 256>>>(emb, mask, out_emb);
    // save_embed = new_emb[saved] @ Wsave^T + bsave, scattered to g_s by original row
    gemm_nt<0, 1, 1><<<gN, 256>>>(out_emb, save_w, save_b, ps, pcnt + 1, 1, 256, pidxs);
    // bank shift/scatter + mask
    bank_kernel<<<(NTRACK * LMEM * 64 + 255) / 256, 256>>>(bank, scores, out_bank);
    mask_kernel<<<(NTRACK * LMEM + 255) / 256, 256>>>(mask, scores, out_mask);
}

// round 5
// speedup vs baseline: 3.3663x; 1.8579x over previous
#include <cuda_runtime.h>
#include <cuda_bf16.h>
#include <math.h>
#include <stdint.h>

#define NTRACK 100000
#define DIM    256
#define LMEM   4

// ---------------- scratch (static __device__ globals: allocation-guard safe) ----
__device__ float g_q  [(size_t)NTRACK * DIM];
__device__ float g_kv [(size_t)NTRACK * LMEM * 2 * DIM];   // compact [4*cnt, 512] = [k|v]
__device__ float g_ctx[(size_t)NTRACK * DIM];
__device__ float g_ao [(size_t)NTRACK * DIM];
__device__ float g_e  [(size_t)NTRACK * DIM];
__device__ float g_h  [(size_t)NTRACK * DIM];
__device__ float g_e2 [(size_t)NTRACK * DIM];
__device__ float g_s  [(size_t)NTRACK * DIM];              // scattered by ORIGINAL row
__device__ int   g_idxv[NTRACK];
__device__ int   g_idxs[NTRACK];
__device__ int   g_cnt[2];          // [0]=valid count, [1]=saved count
__device__ int   g_maskmode;

// ---------------- helpers -------------------------------------------------------
__device__ __forceinline__ uint32_t smem_u32(const void* p)
{
    uint32_t a;
    asm("{ .reg .u64 t; cvta.to.shared.u64 t, %1; cvt.u32.u64 %0, t; }" : "=r"(a) : "l"(p));
    return a;
}
__device__ __forceinline__ void ldm_x4(uint32_t& r0, uint32_t& r1, uint32_t& r2, uint32_t& r3,
                                       uint32_t addr)
{
    asm volatile("ldmatrix.sync.aligned.m8n8.x4.shared.b16 {%0,%1,%2,%3}, [%4];"
                 : "=r"(r0), "=r"(r1), "=r"(r2), "=r"(r3) : "r"(addr));
}
__device__ __forceinline__ void mma_bf16(float* c, uint32_t a0, uint32_t a1, uint32_t a2,
                                         uint32_t a3, uint32_t b0, uint32_t b1)
{
    asm volatile(
        "mma.sync.aligned.m16n8k16.row.col.f32.bf16.bf16.f32 "
        "{%0,%1,%2,%3}, {%4,%5,%6,%7}, {%8,%9}, {%0,%1,%2,%3};"
        : "+f"(c[0]), "+f"(c[1]), "+f"(c[2]), "+f"(c[3])
        : "r"(a0), "r"(a1), "r"(a2), "r"(a3), "r"(b0), "r"(b1));
}

// split fp32x4 into bf16 hi/lo packed pairs
__device__ __forceinline__ void split4(float4 a, uint2& hi, uint2& lo)
{
    __nv_bfloat162 h0 = __float22bfloat162_rn(make_float2(a.x, a.y));
    __nv_bfloat162 h1 = __float22bfloat162_rn(make_float2(a.z, a.w));
    float2 f0 = __bfloat1622float2(h0);
    float2 f1 = __bfloat1622float2(h1);
    __nv_bfloat162 l0 = __float22bfloat162_rn(make_float2(a.x - f0.x, a.y - f0.y));
    __nv_bfloat162 l1 = __float22bfloat162_rn(make_float2(a.z - f1.x, a.w - f1.y));
    hi.x = *(unsigned*)&h0; hi.y = *(unsigned*)&h1;
    lo.x = *(unsigned*)&l0; lo.y = *(unsigned*)&l1;
}

// ---------------- mask dtype detection -----------------------------------------
__global__ void detect_mask_kernel(const unsigned char* __restrict__ m)
{
    __shared__ int s_nonbin, s_oneoff;
    if (threadIdx.x == 0) { s_nonbin = 0; s_oneoff = 0; }
    __syncthreads();
    int nonbin = 0, oneoff = 0;
    const int base = threadIdx.x * 16;
#pragma unroll
    for (int j = 0; j < 16; j++) {
        unsigned char b = m[base + j];
        if (b > 1) nonbin = 1;
        else if (b == 1 && ((base + j) & 3) != 0) oneoff = 1;
    }
    if (nonbin) atomicOr(&s_nonbin, 1);
    if (oneoff) atomicOr(&s_oneoff, 1);
    __syncthreads();
    if (threadIdx.x == 0) {
        g_maskmode = s_nonbin ? 2 : (s_oneoff ? 0 : 1);
        g_cnt[0] = 0;
        g_cnt[1] = 0;
    }
}

__device__ __forceinline__ bool mask_at(const void* __restrict__ m, int i)
{
    const int mode = g_maskmode;
    if (mode == 0) return ((const unsigned char*)m)[i] != 0;
    if (mode == 1) return ((const int*)m)[i] != 0;
    return ((const float*)m)[i] != 0.0f;
}

// ---------------- compaction ----------------------------------------------------
__global__ void compact_kernel(const void* __restrict__ mask,
                               const float* __restrict__ scores)
{
    const int n = blockIdx.x * blockDim.x + threadIdx.x;
    bool v = false, sv = false;
    if (n < NTRACK) {
        v  = !mask_at(mask, n * 4 + 3);
        sv = scores[n] > 0.f;
    }
    const unsigned bv = __ballot_sync(0xFFFFFFFFu, v);
    const unsigned bs = __ballot_sync(0xFFFFFFFFu, sv);
    const int lane = threadIdx.x & 31;
    int basev = 0, bases = 0;
    if (lane == 0) {
        if (bv) basev = atomicAdd(&g_cnt[0], __popc(bv));
        if (bs) bases = atomicAdd(&g_cnt[1], __popc(bs));
    }
    basev = __shfl_sync(0xFFFFFFFFu, basev, 0);
    bases = __shfl_sync(0xFFFFFFFFu, bases, 0);
    const unsigned lt = (1u << lane) - 1u;
    if (v)  g_idxv[basev + __popc(bv & lt)] = n;
    if (sv) g_idxs[bases + __popc(bs & lt)] = n;
}

// ---------------- HMMA GEMM (bf16 split, fp32 accum) ----------------------------
// C[i, bn+n] = sum_k A[map(i),k]*B[bn+n,k] + bias[bn+n]
// Block tile 128(M) x 64(N), K-chunk 32, 8 warps (4m x 2n), warp tile 32x32.
// 3 passes: Ah*Bh + Ah*Bl + Al*Bh.
#define SA 40   // smem row stride in halves (conflict-free: 20 words mod 32 distinct)

template <int RELU, int AMODE, int CMODE>
__global__ __launch_bounds__(256)
void gemm_mma(const float* __restrict__ A, const float* __restrict__ B,
              const float* __restrict__ bias, float* __restrict__ C,
              const int* __restrict__ Mcnt, int mmul, int Nout,
              const int* __restrict__ idx)
{
    const int M = (*Mcnt) * mmul;
    const int bm = blockIdx.y * 128;
    if (bm >= M) return;
    const int bn  = blockIdx.x * 64;
    const int tid = threadIdx.x;
    const int lane = tid & 31;
    const int warp = tid >> 5;
    const int wm = warp >> 1;            // 0..3
    const int wn = warp & 1;             // 0..1
    const int rowbase = wm * 32;
    const int colbase = wn * 32;

    __shared__ __align__(16) __nv_bfloat16 sAh[128 * SA];
    __shared__ __align__(16) __nv_bfloat16 sAl[128 * SA];
    __shared__ __align__(16) __nv_bfloat16 sBh[64 * SA];
    __shared__ __align__(16) __nv_bfloat16 sBl[64 * SA];

    const uint32_t uAh = smem_u32(sAh);
    const uint32_t uAl = smem_u32(sAl);
    const uint32_t uBh = smem_u32(sBh);
    const uint32_t uBl = smem_u32(sBl);

    // ---- per-thread load geometry (4 A rows, 2 B rows; 1 float4 each per chunk)
    const int lr  = tid >> 3;            // 0..31
    const int c4  = (tid & 7) * 4;       // 0..28
    int aRowG[4];                        // global A row per i
    bool aOk[4];
#pragma unroll
    for (int i = 0; i < 4; i++) {
        const int rlog = bm + lr + i * 32;
        aOk[i] = rlog < M;
        int ar = 0;
        if (aOk[i]) {
            if (AMODE == 0)      ar = rlog;
            else if (AMODE == 1) ar = idx[rlog];
            else                 ar = idx[rlog >> 2] * 4 + (rlog & 3);
        }
        aRowG[i] = ar;
    }

    float acc[2][4][4];
#pragma unroll
    for (int mt = 0; mt < 2; mt++)
#pragma unroll
        for (int nt = 0; nt < 4; nt++)
#pragma unroll
            for (int e = 0; e < 4; e++) acc[mt][nt][e] = 0.f;

    // ---- prefetch chunk 0
    float4 pa[4], pb[2];
#pragma unroll
    for (int i = 0; i < 4; i++)
        pa[i] = aOk[i] ? *(const float4*)(A + (size_t)aRowG[i] * 256 + c4)
                       : make_float4(0.f, 0.f, 0.f, 0.f);
#pragma unroll
    for (int j = 0; j < 2; j++)
        pb[j] = *(const float4*)(B + (size_t)(bn + lr + j * 32) * 256 + c4);

    // ldmatrix shared addresses (half index *2 = bytes)
    const uint32_t aHalf = (uint32_t)((rowbase + (lane & 15)) * SA + (lane >> 4) * 8);
    const uint32_t bHalf0 = (uint32_t)((colbase + ((lane >> 4) << 3) + (lane & 7)) * SA
                                       + (((lane >> 3) & 1) << 3));

    for (int kc = 0; kc < 8; kc++) {
        // store prefetched chunk to smem as bf16 hi/lo
        __syncthreads();
#pragma unroll
        for (int i = 0; i < 4; i++) {
            uint2 hi, lo;
            split4(pa[i], hi, lo);
            const int off = (lr + i * 32) * SA + c4;
            *(uint2*)(sAh + off) = hi;
            *(uint2*)(sAl + off) = lo;
        }
#pragma unroll
        for (int j = 0; j < 2; j++) {
            uint2 hi, lo;
            split4(pb[j], hi, lo);
            const int off = (lr + j * 32) * SA + c4;
            *(uint2*)(sBh + off) = hi;
            *(uint2*)(sBl + off) = lo;
        }
        __syncthreads();

        // prefetch next chunk (overlaps with MMA below)
        if (kc < 7) {
            const int kb = (kc + 1) * 32;
#pragma unroll
            for (int i = 0; i < 4; i++)
                pa[i] = aOk[i] ? *(const float4*)(A + (size_t)aRowG[i] * 256 + kb + c4)
                               : make_float4(0.f, 0.f, 0.f, 0.f);
#pragma unroll
            for (int j = 0; j < 2; j++)
                pb[j] = *(const float4*)(B + (size_t)(bn + lr + j * 32) * 256 + kb + c4);
        }

        // MMA over 2 k-steps of 16
#pragma unroll
        for (int ks = 0; ks < 2; ks++) {
            const uint32_t kOffB = (uint32_t)(ks * 16 * 2);  // bytes
            uint32_t ah[2][4], al[2][4];
#pragma unroll
            for (int mt = 0; mt < 2; mt++) {
                const uint32_t byteOff = (aHalf + (uint32_t)(mt * 16 * SA)) * 2 + kOffB;
                ldm_x4(ah[mt][0], ah[mt][1], ah[mt][2], ah[mt][3], uAh + byteOff);
                ldm_x4(al[mt][0], al[mt][1], al[mt][2], al[mt][3], uAl + byteOff);
            }
            uint32_t bh[4][2], bl[4][2];
#pragma unroll
            for (int g = 0; g < 2; g++) {   // each x4 covers 2 n-tiles
                const uint32_t byteOff = (bHalf0 + (uint32_t)(g * 16 * SA)) * 2 + kOffB;
                uint32_t r0, r1, r2, r3;
                ldm_x4(r0, r1, r2, r3, uBh + byteOff);
                bh[g * 2 + 0][0] = r0; bh[g * 2 + 0][1] = r1;
                bh[g * 2 + 1][0] = r2; bh[g * 2 + 1][1] = r3;
                ldm_x4(r0, r1, r2, r3, uBl + byteOff);
                bl[g * 2 + 0][0] = r0; bl[g * 2 + 0][1] = r1;
                bl[g * 2 + 1][0] = r2; bl[g * 2 + 1][1] = r3;
            }
#pragma unroll
            for (int mt = 0; mt < 2; mt++)
#pragma unroll
                for (int nt = 0; nt < 4; nt++) {
                    mma_bf16(acc[mt][nt], ah[mt][0], ah[mt][1], ah[mt][2], ah[mt][3],
                             bh[nt][0], bh[nt][1]);
                    mma_bf16(acc[mt][nt], ah[mt][0], ah[mt][1], ah[mt][2], ah[mt][3],
                             bl[nt][0], bl[nt][1]);
                    mma_bf16(acc[mt][nt], al[mt][0], al[mt][1], al[mt][2], al[mt][3],
                             bh[nt][0], bh[nt][1]);
                }
        }
    }

    // ---- epilogue: direct fragment stores with bias / relu / row scatter -------
    const int q = lane >> 2;             // 0..7
    const int cpair = (lane & 3) * 2;    // 0,2,4,6
#pragma unroll
    for (int mt = 0; mt < 2; mt++) {
#pragma unroll
        for (int half = 0; half < 2; half++) {
            const int rlog = bm + rowbase + mt * 16 + q + half * 8;
            if (rlog >= M) continue;
            const int crow = (CMODE == 1) ? idx[rlog] : rlog;
#pragma unroll
            for (int nt = 0; nt < 4; nt++) {
                const int col = bn + colbase + nt * 8 + cpair;
                float2 bv = *(const float2*)(bias + col);
                float2 v;
                v.x = acc[mt][nt][half * 2 + 0] + bv.x;
                v.y = acc[mt][nt][half * 2 + 1] + bv.y;
                if (RELU) { v.x = fmaxf(v.x, 0.f); v.y = fmaxf(v.y, 0.f); }
                *(float2*)(C + (size_t)crow * Nout + col) = v;
            }
        }
    }
}

// ---------------- tiny attention over compact valid tracks ---------------------
__global__ void attn_kernel(const void* __restrict__ mask)
{
    const int warp = threadIdx.x >> 5, lane = threadIdx.x & 31;
    const int i = blockIdx.x * 8 + warp;
    if (i >= g_cnt[0]) return;
    const int track = g_idxv[i];
    const int h = lane >> 2, l = lane & 3;

    const float* q = g_q + (size_t)i * 256 + h * 32;
    const float* k = g_kv + ((size_t)i * 4 + l) * 512 + h * 32;
    float dot = 0.f;
#pragma unroll
    for (int j = 0; j < 32; j += 4) {
        float4 qv = *(const float4*)(q + j);
        float4 kv = *(const float4*)(k + j);
        dot += qv.x * kv.x + qv.y * kv.y + qv.z * kv.z + qv.w * kv.w;
    }
    float logit = dot * 0.17677669529663687f;
    if (mask_at(mask, track * 4 + l)) logit = -1e9f;

    float m = logit;
    m = fmaxf(m, __shfl_xor_sync(0xFFFFFFFFu, m, 1));
    m = fmaxf(m, __shfl_xor_sync(0xFFFFFFFFu, m, 2));
    float e = expf(logit - m);
    float s = e;
    s += __shfl_xor_sync(0xFFFFFFFFu, s, 1);
    s += __shfl_xor_sync(0xFFFFFFFFu, s, 2);
    float a = e / s;

    const int lbase = lane & ~3;
    float a0 = __shfl_sync(0xFFFFFFFFu, a, lbase + 0);
    float a1 = __shfl_sync(0xFFFFFFFFu, a, lbase + 1);
    float a2 = __shfl_sync(0xFFFFFFFFu, a, lbase + 2);
    float a3 = __shfl_sync(0xFFFFFFFFu, a, lbase + 3);

    const size_t vbase = (size_t)i * 4 * 512 + 256 + lane * 8;
#pragma unroll
    for (int c = 0; c < 8; c += 4) {
        float4 v0 = *(const float4*)(g_kv + vbase + 0 * 512 + c);
        float4 v1 = *(const float4*)(g_kv + vbase + 1 * 512 + c);
        float4 v2 = *(const float4*)(g_kv + vbase + 2 * 512 + c);
        float4 v3 = *(const float4*)(g_kv + vbase + 3 * 512 + c);
        float4 o;
        o.x = a0 * v0.x + a1 * v1.x + a2 * v2.x + a3 * v3.x;
        o.y = a0 * v0.y + a1 * v1.y + a2 * v2.y + a3 * v3.y;
        o.z = a0 * v0.z + a1 * v1.z + a2 * v2.z + a3 * v3.z;
        o.w = a0 * v0.w + a1 * v1.w + a2 * v2.w + a3 * v3.w;
        *(float4*)(g_ctx + (size_t)i * 256 + lane * 8 + c) = o;
    }
}

// ---------------- LayerNorms (compact domain) -----------------------------------
__device__ __forceinline__ float warp_sum(float v)
{
#pragma unroll
    for (int off = 16; off >= 1; off >>= 1)
        v += __shfl_xor_sync(0xFFFFFFFFu, v, off);
    return v;
}

__global__ void add_ln_kernel(const float* __restrict__ X, const float* __restrict__ Y,
                              const float* __restrict__ gw, const float* __restrict__ gb,
                              float* __restrict__ out)
{
    const int warp = threadIdx.x >> 5, lane = threadIdx.x & 31;
    const int i = blockIdx.x * 8 + warp;
    if (i >= g_cnt[0]) return;
    const size_t xb = (size_t)g_idxv[i] * 256 + lane * 8;
    const size_t yb = (size_t)i * 256 + lane * 8;
    float v[8];
    float4 x0 = *(const float4*)(X + xb), x1 = *(const float4*)(X + xb + 4);
    float4 y0 = *(const float4*)(Y + yb), y1 = *(const float4*)(Y + yb + 4);
    v[0] = x0.x + y0.x; v[1] = x0.y + y0.y; v[2] = x0.z + y0.z; v[3] = x0.w + y0.w;
    v[4] = x1.x + y1.x; v[5] = x1.y + y1.y; v[6] = x1.z + y1.z; v[7] = x1.w + y1.w;
    float s = 0.f;
#pragma unroll
    for (int j = 0; j < 8; j++) s += v[j];
    float mu = warp_sum(s) * (1.f / 256.f);
    float sq = 0.f;
#pragma unroll
    for (int j = 0; j < 8; j++) { float d = v[j] - mu; sq += d * d; }
    float r = rsqrtf(warp_sum(sq) * (1.f / 256.f) + 1e-5f);
#pragma unroll
    for (int j = 0; j < 8; j++)
        out[yb + j] = (v[j] - mu) * r * gw[lane * 8 + j] + gb[lane * 8 + j];
}

__global__ void ln2_scatter_kernel(const float* __restrict__ X, const float* __restrict__ Y,
                                   const float* __restrict__ gw, const float* __restrict__ gb,
                                   float* __restrict__ out)
{
    const int warp = threadIdx.x >> 5, lane = threadIdx.x & 31;
    const int i = blockIdx.x * 8 + warp;
    if (i >= g_cnt[0]) return;
    const size_t cb = (size_t)i * 256 + lane * 8;
    const size_t ob = (size_t)g_idxv[i] * 256 + lane * 8;
    float v[8];
    float4 x0 = *(const float4*)(X + cb), x1 = *(const float4*)(X + cb + 4);
    float4 y0 = *(const float4*)(Y + cb), y1 = *(const float4*)(Y + cb + 4);
    v[0] = x0.x + y0.x; v[1] = x0.y + y0.y; v[2] = x0.z + y0.z; v[3] = x0.w + y0.w;
    v[4] = x1.x + y1.x; v[5] = x1.y + y1.y; v[6] = x1.z + y1.z; v[7] = x1.w + y1.w;
    float s = 0.f;
#pragma unroll
    for (int j = 0; j < 8; j++) s += v[j];
    float mu = warp_sum(s) * (1.f / 256.f);
    float sq = 0.f;
#pragma unroll
    for (int j = 0; j < 8; j++) { float d = v[j] - mu; sq += d * d; }
    float r = rsqrtf(warp_sum(sq) * (1.f / 256.f) + 1e-5f);
#pragma unroll
    for (int j = 0; j < 8; j++)
        out[ob + j] = (v[j] - mu) * r * gw[lane * 8 + j] + gb[lane * 8 + j];
}

__global__ void copy_invalid_kernel(const float* __restrict__ emb,
                                    const void* __restrict__ mask,
                                    float* __restrict__ out)
{
    const int idx = blockIdx.x * blockDim.x + threadIdx.x;
    if (idx >= NTRACK * 64) return;
    const int n = idx >> 6;
    if (!mask_at(mask, n * 4 + 3)) return;
    ((float4*)out)[idx] = ((const float4*)emb)[idx];
}

// ---------------- bank shift/scatter --------------------------------------------
__global__ void bank_kernel(const float* __restrict__ mem_bank,
                            const float* __restrict__ scores,
                            float* __restrict__ out_bank)
{
    const int idx = blockIdx.x * blockDim.x + threadIdx.x;
    if (idx >= NTRACK * LMEM * 64) return;
    const int n = idx >> 8;
    const int l = (idx >> 6) & 3;
    const int c = idx & 63;
    const bool saved = scores[n] > 0.f;
    const float4* mb4 = (const float4*)mem_bank;
    float4 val;
    if (saved) {
        if (l < 3) val = mb4[(size_t)n * 256 + (l + 1) * 64 + c];
        else       val = ((const float4*)g_s)[(size_t)n * 64 + c];
    } else {
        val = mb4[idx];
    }
    ((float4*)out_bank)[idx] = val;
}

__global__ void mask_kernel(const void* __restrict__ mask,
                            const float* __restrict__ scores,
                            float* __restrict__ out_mask)
{
    const int idx = blockIdx.x * blockDim.x + threadIdx.x;
    if (idx >= NTRACK * LMEM) return;
    const int n = idx >> 2, l = idx & 3;
    const bool saved = scores[n] > 0.f;
    float v;
    if (saved) v = (l < 3) ? (mask_at(mask, n * 4 + l + 1) ? 1.f : 0.f) : 0.f;
    else       v = mask_at(mask, idx) ? 1.f : 0.f;
    out_mask[idx] = v;
}

// ---------------- launcher ------------------------------------------------------
extern "C" void kernel_launch(void* const* d_in, const int* in_sizes, int n_in,
                              void* d_out, int out_size)
{
    const float* emb    = (const float*)d_in[0];
    const float* scores = (const float*)d_in[1];
    const float* bank   = (const float*)d_in[2];
    const void*  mask   = (const void*)d_in[3];
    const float* save_w = (const float*)d_in[4];
    const float* save_b = (const float*)d_in[5];
    const float* in_w   = (const float*)d_in[6];
    const float* in_b   = (const float*)d_in[7];
    const float* out_w  = (const float*)d_in[8];
    const float* out_b  = (const float*)d_in[9];
    const float* fc1_w  = (const float*)d_in[10];
    const float* fc1_b  = (const float*)d_in[11];
    const float* fc2_w  = (const float*)d_in[12];
    const float* fc2_b  = (const float*)d_in[13];
    const float* ln1_g  = (const float*)d_in[14];
    const float* ln1_b  = (const float*)d_in[15];
    const float* ln2_g  = (const float*)d_in[16];
    const float* ln2_b  = (const float*)d_in[17];

    float* out_emb  = (float*)d_out;
    float* out_bank = out_emb + (size_t)NTRACK * DIM;
    float* out_mask = out_bank + (size_t)NTRACK * LMEM * DIM;

    float *pq, *pkv, *pctx, *pao, *pe, *ph, *pe2, *ps;
    int *pidxv, *pidxs, *pcnt;
    cudaGetSymbolAddress((void**)&pq,   g_q);
    cudaGetSymbolAddress((void**)&pkv,  g_kv);
    cudaGetSymbolAddress((void**)&pctx, g_ctx);
    cudaGetSymbolAddress((void**)&pao,  g_ao);
    cudaGetSymbolAddress((void**)&pe,   g_e);
    cudaGetSymbolAddress((void**)&ph,   g_h);
    cudaGetSymbolAddress((void**)&pe2,  g_e2);
    cudaGetSymbolAddress((void**)&ps,   g_s);
    cudaGetSymbolAddress((void**)&pidxv, g_idxv);
    cudaGetSymbolAddress((void**)&pidxs, g_idxs);
    cudaGetSymbolAddress((void**)&pcnt,  g_cnt);

    const dim3 gN(4, (NTRACK + 127) / 128);              // Nout=256 (64-col blocks)
    const dim3 gKV(8, (NTRACK * LMEM + 127) / 128);      // Nout=512, M<=4N
    const int rowBlocks = (NTRACK + 7) / 8;

    detect_mask_kernel<<<1, 256>>>((const unsigned char*)mask);
    compact_kernel<<<(NTRACK + 255) / 256, 256>>>(mask, scores);

    // q = emb[valid] @ Wq^T + bq
    gemm_mma<0, 1, 0><<<gN, 256>>>(emb, in_w, in_b, pq, pcnt, 1, 256, pidxv);
    // [k|v] = bank[valid] @ Wkv^T
    gemm_mma<0, 2, 0><<<gKV, 256>>>(bank, in_w + 256 * 256, in_b + 256, pkv, pcnt, 4, 512, pidxv);
    // attention -> ctx
    attn_kernel<<<rowBlocks, 256>>>(mask);
    // attn_out = ctx @ Wo^T + bo
    gemm_mma<0, 0, 0><<<gN, 256>>>(pctx, out_w, out_b, pao, pcnt, 1, 256, pidxv);
    // e = LN1(emb[idx] + attn_out)
    add_ln_kernel<<<rowBlocks, 256>>>(emb, pao, ln1_g, ln1_b, pe);
    // h = relu(e @ W1^T + b1)
    gemm_mma<1, 0, 0><<<gN, 256>>>(pe, fc1_w, fc1_b, ph, pcnt, 1, 256, pidxv);
    // e2 = h @ W2^T + b2
    gemm_mma<0, 0, 0><<<gN, 256>>>(ph, fc2_w, fc2_b, pe2, pcnt, 1, 256, pidxv);
    // new_emb
    ln2_scatter_kernel<<<rowBlocks, 256>>>(pe, pe2, ln2_g, ln2_b, out_emb);
    copy_invalid_kernel<<<(NTRACK * 64 + 255) / 256, 256>>>(emb, mask, out_emb);
    // save_embed (scatter to g_s by original row)
    gemm_mma<0, 1, 1><<<gN, 256>>>(out_emb, save_w, save_b, ps, pcnt + 1, 1, 256, pidxs);
    // bank shift/scatter + mask
    bank_kernel<<<(NTRACK * LMEM * 64 + 255) / 256, 256>>>(bank, scores, out_bank);
    mask_kernel<<<(NTRACK * LMEM + 255) / 256, 256>>>(mask, scores, out_mask);
}